// round 1
// baseline (speedup 1.0000x reference)
#include <cuda_runtime.h>

// Problem constants
#define B_DIM   32
#define T_DIM   128
#define C_DIM   64
#define F_DIM   64
#define K_DIM   128
#define KH      3
#define CP      62          // C - KH + 1
#define N_TOTAL (B_DIM * T_DIM)   // 4096 fused batch*time rows
#define KTOT    (KH * F_DIM)      // 192 reduction length
#define BN_EPS  1e-3f

#define N_PER_CTA 4
#define THREADS   256

// dynamic smem layout: ws[192*128] floats, then xs[66*64] floats
#define WS_ELEMS (KTOT * K_DIM)        // 24576
#define XS_ROWS  66                    // 64 + 2 zero pad rows
#define XS_ELEMS (XS_ROWS * F_DIM)     // 4224
#define SMEM_BYTES ((WS_ELEMS + XS_ELEMS) * 4)

__global__ __launch_bounds__(THREADS, 1)
void tccnn_kernel(const float* __restrict__ x,
                  const float* __restrict__ conv_w,
                  const float* __restrict__ conv_b,
                  const float* __restrict__ bn_gamma,
                  const float* __restrict__ bn_beta,
                  const float* __restrict__ bn_mean,
                  const float* __restrict__ bn_var,
                  float* __restrict__ out)
{
    extern __shared__ float smem[];
    float* ws = smem;                 // [192][128]
    float* xs = smem + WS_ELEMS;      // [66][64]

    const int tid = threadIdx.x;
    const int tx  = tid & 15;         // k-group: k in {4tx..4tx+3} U {64+4tx..64+4tx+3}
    const int ty  = tid >> 4;         // cp-group: cp in {4ty..4ty+3}

    // ---- Load weights into smem (layout identical to conv_w memory) ----
    {
        const float4* w4  = (const float4*)conv_w;
        float4*       ws4 = (float4*)ws;
        #pragma unroll
        for (int i = 0; i < WS_ELEMS / 4 / THREADS; ++i)   // 24 iters
            ws4[tid + i * THREADS] = w4[tid + i * THREADS];
    }

    // ---- Zero the two pad rows of the x tile (rows 64,65 -> 128 floats) ----
    if (tid < 128) xs[64 * F_DIM + tid] = 0.0f;

    // ---- Per-thread conv bias for its 8 k columns ----
    float bias[8];
    #pragma unroll
    for (int j = 0; j < 4; ++j) {
        bias[j]     = conv_b[4 * tx + j];
        bias[4 + j] = conv_b[64 + 4 * tx + j];
    }

    const int n0 = blockIdx.x * N_PER_CTA;

    for (int ni = 0; ni < N_PER_CTA; ++ni) {
        const int n = n0 + ni;
        const int t = n & (T_DIM - 1);

        // Wait for all readers of previous tile (and, on iter 0, cover the
        // weight-load + pad-row writes), then load this n's x tile.
        __syncthreads();
        {
            const float4* xg4 = (const float4*)(x + (size_t)n * (C_DIM * F_DIM));
            float4*       xs4 = (float4*)xs;
            #pragma unroll
            for (int i = 0; i < (C_DIM * F_DIM) / 4 / THREADS; ++i)   // 4 iters
                xs4[tid + i * THREADS] = xg4[tid + i * THREADS];
        }
        __syncthreads();

        // BN affine for this t (uniform across block)
        const float inv = rsqrtf(bn_var[t] + BN_EPS);
        const float s   = bn_gamma[t] * inv;
        const float sh  = bn_beta[t] - bn_mean[t] * s;

        float acc[4][8];
        #pragma unroll
        for (int r = 0; r < 4; ++r)
            #pragma unroll
            for (int j = 0; j < 8; ++j)
                acc[r][j] = 0.0f;

        // ---- Main reduction: 48 groups of 4 contiguous kw ----
        // kq = kh*16 + kw4; kidx = kh*64 + kw4*4 + q
        #pragma unroll 4
        for (int kq = 0; kq < 48; ++kq) {
            const int kh  = kq >> 4;
            const int kw4 = kq & 15;

            float4 a[4];
            #pragma unroll
            for (int r = 0; r < 4; ++r)
                a[r] = ((const float4*)(xs + (4 * ty + r + kh) * F_DIM))[kw4];

            #pragma unroll
            for (int q = 0; q < 4; ++q) {
                const int kidx = kh * 64 + kw4 * 4 + q;
                const float4 b0 = ((const float4*)(ws + kidx * K_DIM))[tx];
                const float4 b1 = ((const float4*)(ws + kidx * K_DIM))[16 + tx];
                #pragma unroll
                for (int r = 0; r < 4; ++r) {
                    const float av = (q == 0) ? a[r].x : (q == 1) ? a[r].y
                                   : (q == 2) ? a[r].z : a[r].w;
                    acc[r][0] = fmaf(av, b0.x, acc[r][0]);
                    acc[r][1] = fmaf(av, b0.y, acc[r][1]);
                    acc[r][2] = fmaf(av, b0.z, acc[r][2]);
                    acc[r][3] = fmaf(av, b0.w, acc[r][3]);
                    acc[r][4] = fmaf(av, b1.x, acc[r][4]);
                    acc[r][5] = fmaf(av, b1.y, acc[r][5]);
                    acc[r][6] = fmaf(av, b1.z, acc[r][6]);
                    acc[r][7] = fmaf(av, b1.w, acc[r][7]);
                }
            }
        }

        // ---- Epilogue: bias + BN + ReLU, vectorized store ----
        float* outn = out + (size_t)n * (CP * K_DIM);
        #pragma unroll
        for (int r = 0; r < 4; ++r) {
            const int cp = 4 * ty + r;
            if (cp < CP) {
                float4 o0, o1;
                o0.x = fmaxf((acc[r][0] + bias[0]) * s + sh, 0.0f);
                o0.y = fmaxf((acc[r][1] + bias[1]) * s + sh, 0.0f);
                o0.z = fmaxf((acc[r][2] + bias[2]) * s + sh, 0.0f);
                o0.w = fmaxf((acc[r][3] + bias[3]) * s + sh, 0.0f);
                o1.x = fmaxf((acc[r][4] + bias[4]) * s + sh, 0.0f);
                o1.y = fmaxf((acc[r][5] + bias[5]) * s + sh, 0.0f);
                o1.z = fmaxf((acc[r][6] + bias[6]) * s + sh, 0.0f);
                o1.w = fmaxf((acc[r][7] + bias[7]) * s + sh, 0.0f);
                ((float4*)(outn + cp * K_DIM))[tx]      = o0;
                ((float4*)(outn + cp * K_DIM))[16 + tx] = o1;
            }
        }
    }
}

extern "C" void kernel_launch(void* const* d_in, const int* in_sizes, int n_in,
                              void* d_out, int out_size)
{
    const float* x        = (const float*)d_in[0];
    const float* conv_w   = (const float*)d_in[1];
    const float* conv_b   = (const float*)d_in[2];
    const float* bn_gamma = (const float*)d_in[3];
    const float* bn_beta  = (const float*)d_in[4];
    const float* bn_mean  = (const float*)d_in[5];
    const float* bn_var   = (const float*)d_in[6];
    float* out = (float*)d_out;

    cudaFuncSetAttribute(tccnn_kernel,
                         cudaFuncAttributeMaxDynamicSharedMemorySize, SMEM_BYTES);

    tccnn_kernel<<<N_TOTAL / N_PER_CTA, THREADS, SMEM_BYTES>>>(
        x, conv_w, conv_b, bn_gamma, bn_beta, bn_mean, bn_var, out);
}

// round 6
// speedup vs baseline: 2.5308x; 2.5308x over previous
#include <cuda_runtime.h>
#include <cstdint>

// ---- problem constants ----
#define B_DIM   32
#define T_DIM   128
#define C_DIM   64
#define F_DIM   64
#define K_DIM   128          // filters = GEMM M
#define CP      62
#define NP      64           // padded cp = GEMM N
#define KTOT    192          // reduction length
#define N_TOTAL 4096
#define BN_EPS  1e-3f

#define NPC     4            // fused rows per CTA
#define THREADS 256
#define NKC     24           // K chunks of 8

// smem float layout:
//   A: [24][128][8]  = 24576 floats @ 0        (weights, K-permuted)
//   B0: [24][64][8]  = 12288 floats @ 24576
//   B1: [24][64][8]  = 12288 floats @ 36864
#define A_ELEMS  (NKC * K_DIM * 8)
#define B_ELEMS  (NKC * NP * 8)
#define SMEM_FLOATS (A_ELEMS + 2 * B_ELEMS)
#define SMEM_BYTES  (SMEM_FLOATS * 4)          // 196608

// round fp32 -> tf32 (round to nearest) kept in a float register
__device__ __forceinline__ float tf32r(float v) {
    uint32_t u;
    asm("cvt.rna.tf32.f32 %0, %1;" : "=r"(u) : "f"(v));
    return __uint_as_float(u);
}

// B-tile fill: B(cp, kk=kh*64+kw) = x[n, cp+kh, kw], permuted K chunks.
// thread -> (cp = tid>>2, q = tid&3 selects kw quarter [16q,16q+16))
__device__ __forceinline__ void fill_b(float* __restrict__ bs,
                                       const float* __restrict__ x,
                                       int n, int tid) {
    const int cp = tid >> 2;
    const int q  = tid & 3;
    const float4 z4 = make_float4(0.f, 0.f, 0.f, 0.f);
    #pragma unroll
    for (int kh = 0; kh < 3; ++kh) {
        const int c = cp + kh;
        const bool ok = (c < C_DIM);
        const float4* src = (const float4*)(x + (size_t)n * (C_DIM * F_DIM) + c * F_DIM) + 4 * q;
        const float4 a0 = ok ? src[0] : z4;
        const float4 a1 = ok ? src[1] : z4;
        const float4 a2 = ok ? src[2] : z4;
        const float4 a3 = ok ? src[3] : z4;
        // chunk kc = kh*8 + 2q + jj covers kw = 16q + 8*jj + c (c = 0..7)
        // within-chunk position: pos 2e holds k=e (lo), 2e+1 holds k=e+4 (hi)
        float2* d0 = (float2*)(bs + (kh * 8 + 2 * q) * (NP * 8) + cp * 8);
        float2* d1 = (float2*)(bs + (kh * 8 + 2 * q + 1) * (NP * 8) + cp * 8);
        d0[0] = make_float2(tf32r(a0.x), tf32r(a1.x));
        d0[1] = make_float2(tf32r(a0.y), tf32r(a1.y));
        d0[2] = make_float2(tf32r(a0.z), tf32r(a1.z));
        d0[3] = make_float2(tf32r(a0.w), tf32r(a1.w));
        d1[0] = make_float2(tf32r(a2.x), tf32r(a3.x));
        d1[1] = make_float2(tf32r(a2.y), tf32r(a3.y));
        d1[2] = make_float2(tf32r(a2.z), tf32r(a3.z));
        d1[3] = make_float2(tf32r(a2.w), tf32r(a3.w));
    }
}

__global__ __launch_bounds__(THREADS, 1)
void tccnn_mma_kernel(const float* __restrict__ x,
                      const float* __restrict__ conv_w,
                      const float* __restrict__ conv_b,
                      const float* __restrict__ bn_gamma,
                      const float* __restrict__ bn_beta,
                      const float* __restrict__ bn_mean,
                      const float* __restrict__ bn_var,
                      float* __restrict__ out)
{
    extern __shared__ float smem[];
    float* As = smem;                        // [24][128][8]
    float* Bs0 = smem + A_ELEMS;
    float* Bs1 = smem + A_ELEMS + B_ELEMS;

    const int tid  = threadIdx.x;
    const int lane = tid & 31;
    const int wid  = tid >> 5;
    const int m0   = (wid & 3) * 32;         // warp M origin (filters)
    const int n0   = (wid >> 2) * 32;        // warp N origin (cp)

    // ---- stage weights: A(m, kk) = conv_w[kk*128 + m], permuted K chunks ----
    {
        const int m    = tid & 127;
        const int kk0  = (tid >> 7) * 96;
        #pragma unroll 4
        for (int j = 0; j < 96; ++j) {
            const int kk = kk0 + j;
            const float v = tf32r(conv_w[kk * K_DIM + m]);
            const int pos = ((kk & 3) << 1) | ((kk >> 2) & 1);   // perm within chunk
            As[(kk >> 3) * (K_DIM * 8) + m * 8 + pos] = v;
        }
    }

    // per-thread bias values (rows of C this thread owns)
    const int m_base = m0 + (lane >> 2);
    float bias_v[2][2];
    #pragma unroll
    for (int mt = 0; mt < 2; ++mt) {
        bias_v[mt][0] = conv_b[m_base + 16 * mt];
        bias_v[mt][1] = conv_b[m_base + 16 * mt + 8];
    }

    const int n0c = blockIdx.x * NPC;

    fill_b(Bs0, x, n0c, tid);
    __syncthreads();

    for (int i = 0; i < NPC; ++i) {
        const int n = n0c + i;

        // overlap: fill next B buffer while this iteration's MMAs run
        if (i + 1 < NPC)
            fill_b(((i + 1) & 1) ? Bs1 : Bs0, x, n + 1, tid);

        const float* Bs = (i & 1) ? Bs1 : Bs0;

        float acc[2][4][4];
        #pragma unroll
        for (int mt = 0; mt < 2; ++mt)
            #pragma unroll
            for (int nt = 0; nt < 4; ++nt)
                #pragma unroll
                for (int r = 0; r < 4; ++r)
                    acc[mt][nt][r] = 0.0f;

        #pragma unroll
        for (int kc = 0; kc < NKC; ++kc) {
            uint32_t a[2][4];
            #pragma unroll
            for (int mt = 0; mt < 2; ++mt) {
                const float2 lo = *(const float2*)(As + kc * (K_DIM * 8)
                                     + (m0 + 16 * mt + (lane >> 2)) * 8 + 2 * (lane & 3));
                const float2 hi = *(const float2*)(As + kc * (K_DIM * 8)
                                     + (m0 + 16 * mt + 8 + (lane >> 2)) * 8 + 2 * (lane & 3));
                a[mt][0] = __float_as_uint(lo.x);
                a[mt][1] = __float_as_uint(hi.x);
                a[mt][2] = __float_as_uint(lo.y);
                a[mt][3] = __float_as_uint(hi.y);
            }
            #pragma unroll
            for (int nt = 0; nt < 4; ++nt) {
                const float2 bb = *(const float2*)(Bs + kc * (NP * 8)
                                     + (n0 + 8 * nt + (lane >> 2)) * 8 + 2 * (lane & 3));
                const uint32_t b0 = __float_as_uint(bb.x);
                const uint32_t b1 = __float_as_uint(bb.y);
                #pragma unroll
                for (int mt = 0; mt < 2; ++mt) {
                    asm volatile(
                        "mma.sync.aligned.m16n8k8.row.col.f32.tf32.tf32.f32 "
                        "{%0,%1,%2,%3}, {%4,%5,%6,%7}, {%8,%9}, {%0,%1,%2,%3};"
                        : "+f"(acc[mt][nt][0]), "+f"(acc[mt][nt][1]),
                          "+f"(acc[mt][nt][2]), "+f"(acc[mt][nt][3])
                        : "r"(a[mt][0]), "r"(a[mt][1]), "r"(a[mt][2]), "r"(a[mt][3]),
                          "r"(b0), "r"(b1));
                }
            }
        }

        // ---- epilogue: bias + BN(t) + ReLU, direct STG ----
        {
            const int t = n & (T_DIM - 1);
            const float inv = rsqrtf(bn_var[t] + BN_EPS);
            const float s   = bn_gamma[t] * inv;
            const float sh  = bn_beta[t] - bn_mean[t] * s;
            float* outn = out + (size_t)n * (CP * K_DIM);

            #pragma unroll
            for (int mt = 0; mt < 2; ++mt) {
                const int m_lo = m_base + 16 * mt;
                const int m_hi = m_lo + 8;
                #pragma unroll
                for (int nt = 0; nt < 4; ++nt) {
                    const int cp0 = n0 + 8 * nt + 2 * (lane & 3);
                    const float v0 = fmaxf((acc[mt][nt][0] + bias_v[mt][0]) * s + sh, 0.f);
                    const float v1 = fmaxf((acc[mt][nt][1] + bias_v[mt][0]) * s + sh, 0.f);
                    const float v2 = fmaxf((acc[mt][nt][2] + bias_v[mt][1]) * s + sh, 0.f);
                    const float v3 = fmaxf((acc[mt][nt][3] + bias_v[mt][1]) * s + sh, 0.f);
                    if (cp0 < CP) {
                        outn[cp0 * K_DIM + m_lo] = v0;
                        outn[cp0 * K_DIM + m_hi] = v2;
                    }
                    if (cp0 + 1 < CP) {
                        outn[(cp0 + 1) * K_DIM + m_lo] = v1;
                        outn[(cp0 + 1) * K_DIM + m_hi] = v3;
                    }
                }
            }
        }
        __syncthreads();   // fill(i+1) complete + all reads of Bs done before reuse
    }
}

extern "C" void kernel_launch(void* const* d_in, const int* in_sizes, int n_in,
                              void* d_out, int out_size)
{
    const float* x        = (const float*)d_in[0];
    const float* conv_w   = (const float*)d_in[1];
    const float* conv_b   = (const float*)d_in[2];
    const float* bn_gamma = (const float*)d_in[3];
    const float* bn_beta  = (const float*)d_in[4];
    const float* bn_mean  = (const float*)d_in[5];
    const float* bn_var   = (const float*)d_in[6];
    float* out = (float*)d_out;

    cudaFuncSetAttribute(tccnn_mma_kernel,
                         cudaFuncAttributeMaxDynamicSharedMemorySize, SMEM_BYTES);

    tccnn_mma_kernel<<<N_TOTAL / NPC, THREADS, SMEM_BYTES>>>(
        x, conv_w, conv_b, bn_gamma, bn_beta, bn_mean, bn_var, out);
}